// round 16
// baseline (speedup 1.0000x reference)
#include <cuda_runtime.h>
#include <stdint.h>

// ---------------------------------------------------------------------------
// extract_high_freq via db4 wavelet, [96][512][512] fp32 — single fused kernel.
//   P0: lo_s[i] = row-DWT-approx(data[mir(R0-6+i)]); hi_s for own rows
//   P1: lr_s[tt] = column correction (two-step in registers)
//   P2: out[t]  = row-IDWT(lr_s[tt], 2*hi_s[tt]) — hi half computed BEFORE
//       the P1->P2 barrier (depends only on hi_s), lr half after.
// ---------------------------------------------------------------------------

#define N     512
#define M     259          // (512+7)/2
#define NIMG  96

#define TR    16           // output rows per block
#define LOR   28           // lo rows: global [R0-6, R0+21]
#define KS    260          // smem row stride (floats)

#define DL0 (-0.010597401784997278f)
#define DL1 ( 0.032883011666982945f)
#define DL2 ( 0.030841381835986965f)
#define DL3 (-0.18703481171888114f)
#define DL4 (-0.02798376941698385f)
#define DL5 ( 0.6308807679295904f)
#define DL6 ( 0.7148465705525415f)
#define DL7 ( 0.23037781330885523f)

// REC_LO[j] = DEC_LO[7-j] ; REC_HI[j] = (-1)^j * DEC_LO[j]
#define REC_LO_INIT  { DL7,  DL6,  DL5,  DL4,  DL3,  DL2,  DL1,  DL0 }
#define REC_HI_INIT  { DL0, -DL1,  DL2, -DL3,  DL4, -DL5,  DL6, -DL7 }
#define REC_HI2_INIT { 2*DL0, -2*DL1, 2*DL2, -2*DL3, 2*DL4, -2*DL5, 2*DL6, -2*DL7 }

// packed f32x2 helpers (sm_100+)
__device__ __forceinline__ unsigned long long pk2(float lo, float hi) {
    unsigned long long r;
    asm("mov.b64 %0, {%1, %2};" : "=l"(r) : "f"(lo), "f"(hi));
    return r;
}
__device__ __forceinline__ void fma2(unsigned long long& d,
                                     unsigned long long a,
                                     unsigned long long b) {
    asm("fma.rn.f32x2 %0, %1, %2, %3;" : "=l"(d) : "l"(a), "l"(b), "l"(d));
}

__device__ __forceinline__ int mirN(int i) {
    if (i < 0)  i = -1 - i;
    if (i >= N) i = 2 * N - 1 - i;
    return i;
}

__global__ void __launch_bounds__(512, 3) k_all(const float* __restrict__ x,
                                                float* __restrict__ out)
{
    extern __shared__ float sm[];
    float* lo_s = sm;                      // [LOR][KS]
    float* hi_s = sm + LOR * KS;           // [TR][KS]
    float* lr_s = sm + (LOR + TR) * KS;    // [TR][KS]

    const int tx  = threadIdx.x;           // 0..127
    const int ty  = threadIdx.y;           // 0..3
    const int tid = ty * 128 + tx;
    const int img = blockIdx.y;
    const int R0  = blockIdx.x * TR;

    const float* ximg = x + (size_t)img * N * N;

    const float rl[8] = REC_LO_INIT;
    const float rh[8] = REC_HI_INIT;

    // ---------------- P0: row DWT of 28 data rows into smem ----------------
    {
        const int jj = tid & 63;           // k = 4jj..4jj+3
        const int rg = tid >> 6;           // 0..7

        auto body = [&](int i) {
            const int gr = mirN(R0 - 6 + i);
            const float* xr = ximg + (size_t)gr * N;
            const bool own = (i >= 6) && (i < 6 + TR);
            float* lo = lo_s + i * KS;
            float* hi = hi_s + (i - 6) * KS;

            if (jj >= 1) {
                const float2 w0 = *(const float2*)(xr + 8 * jj - 6);
                const float4 w1 = *(const float4*)(xr + 8 * jj - 4);
                const float4 w2 = *(const float4*)(xr + 8 * jj);
                const float4 w3 = *(const float4*)(xr + 8 * jj + 4);
                const float win[14] = { w0.x, w0.y,
                                        w1.x, w1.y, w1.z, w1.w,
                                        w2.x, w2.y, w2.z, w2.w,
                                        w3.x, w3.y, w3.z, w3.w };
                float a[4];
#pragma unroll
                for (int q = 0; q < 4; ++q) {
                    float aa = 0.f;
#pragma unroll
                    for (int u = 0; u < 8; ++u)
                        aa = fmaf(win[2 * q + u], rl[u], aa);
                    a[q] = aa;
                }
                *(float4*)(lo + 4 * jj) = make_float4(a[0], a[1], a[2], a[3]);
                if (own) {
                    float d[4];
#pragma unroll
                    for (int q = 0; q < 4; ++q) {
                        float dd = 0.f;
#pragma unroll
                        for (int u = 0; u < 8; ++u)
                            dd = fmaf(win[2 * q + u], rh[u], dd);
                        d[q] = dd;
                    }
                    *(float4*)(hi + 4 * jj) = make_float4(d[0], d[1], d[2], d[3]);
                }
            } else {
                float a[4], d[4];
#pragma unroll
                for (int q = 0; q < 4; ++q) {
                    const int e0 = 2 * q - 6;
                    float aa = 0.f, dd = 0.f;
#pragma unroll
                    for (int u = 0; u < 8; ++u) {
                        const float v = xr[mirN(e0 + u)];
                        aa = fmaf(v, rl[u], aa);
                        dd = fmaf(v, rh[u], dd);
                    }
                    a[q] = aa; d[q] = dd;
                }
                *(float4*)(lo) = make_float4(a[0], a[1], a[2], a[3]);
                if (own)
                    *(float4*)(hi) = make_float4(d[0], d[1], d[2], d[3]);
            }

            if (jj >= 1 && jj <= 3) {                // tail k = 256..258
                const int kk = 255 + jj;
                const int e0 = 2 * kk - 6;
                float aa = 0.f, dd = 0.f;
#pragma unroll
                for (int u = 0; u < 8; ++u) {
                    const float v = xr[mirN(e0 + u)];
                    aa = fmaf(v, rl[u], aa);
                    dd = fmaf(v, rh[u], dd);
                }
                lo[kk] = aa;
                if (own) hi[kk] = dd;
            }
        };

        body(rg);
        body(rg + 8);
        body(rg + 16);
        if (rg < 4) body(rg + 24);
    }
    __syncthreads();

    // ------- P1: column correction, two-step in registers ------------------
    // half h = tid>>8 owns output rows 8h..8h+7 of column k via a 20-row
    // register window w[0..19] (lo_s rows 8h..8h+19).
    {
        const int h  = tid >> 8;               // 0..1
        const int c0 = tid & 255;              // 0..255
        const int rbase = 8 * h;
        for (int k = c0; k < M; k += 256) {
            float w[20];
#pragma unroll
            for (int i = 0; i < 20; ++i)
                w[i] = lo_s[(rbase + i) * KS + k];

            float ds[7];
#pragma unroll
            for (int j = 0; j < 7; ++j) {
                float d = 0.f;
#pragma unroll
                for (int m = 0; m < 8; ++m)
                    d = fmaf(w[2 * j + m], rh[m], d);
                ds[j] = d;
            }

#pragma unroll
            for (int r = 0; r < 8; ++r) {      // output row rbase + r
                const int q0 = r >> 1;
                float acc;
                if ((r & 1) == 0) {
                    acc = fmaf(ds[q0],     rh[6], w[r + 6]);
                    acc = fmaf(ds[q0 + 1], rh[4], acc);
                    acc = fmaf(ds[q0 + 2], rh[2], acc);
                    acc = fmaf(ds[q0 + 3], rh[0], acc);
                } else {
                    acc = fmaf(ds[q0],     rh[7], w[r + 6]);
                    acc = fmaf(ds[q0 + 1], rh[5], acc);
                    acc = fmaf(ds[q0 + 2], rh[3], acc);
                    acc = fmaf(ds[q0 + 3], rh[1], acc);
                }
                lr_s[(rbase + r) * KS + k] = acc;
            }
        }
    }

    // ------- P2 (pre-barrier half): hi-branch accumulation -----------------
    // Depends only on hi_s (stable since the P0 barrier). Fills the barrier
    // shadow and halves the post-barrier LDS burst + dependent chain.
    const int jj = tid & 63;                // cols 8jj..8jj+7, u0 = 4jj
    const int rg = tid >> 6;                // 0..7; rows rg and rg+8
    float* out_img = out + (size_t)img * N * N;
    const float rh2[8] = REC_HI2_INIT;

    unsigned long long o2a[4], o2b[4];

    auto hi_part = [&](int tt, unsigned long long* o2) {
        const float* hr = hi_s + tt * KS + 4 * jj;
        const float4 d03 = *(const float4*)hr;
        const float2 d45 = *(const float2*)(hr + 4);
        const float  d6  = hr[6];
        const float d[7] = { d03.x, d03.y, d03.z, d03.w, d45.x, d45.y, d6 };
#pragma unroll
        for (int p = 0; p < 4; ++p) {
            unsigned long long acc = 0ull;
#pragma unroll
            for (int i = 0; i < 4; ++i)
                fma2(acc, pk2(d[p + i], d[p + i]),
                          pk2(rh2[6 - 2 * i], rh2[7 - 2 * i]));
            o2[p] = acc;
        }
    };

    hi_part(rg,     o2a);
    hi_part(rg + 8, o2b);

    __syncthreads();

    // ------- P2 (post-barrier half): lr-branch + store ---------------------
    {
        auto lr_part = [&](int tt, unsigned long long* o2) {
            const float* ar = lr_s + tt * KS + 4 * jj;
            const float4 a03 = *(const float4*)ar;
            const float2 a45 = *(const float2*)(ar + 4);
            const float  a6  = ar[6];
            const float a[7] = { a03.x, a03.y, a03.z, a03.w, a45.x, a45.y, a6 };
#pragma unroll
            for (int p = 0; p < 4; ++p) {
                unsigned long long acc = o2[p];
#pragma unroll
                for (int i = 0; i < 4; ++i)
                    fma2(acc, pk2(a[p + i], a[p + i]),
                              pk2(rl[6 - 2 * i], rl[7 - 2 * i]));
                o2[p] = acc;
            }
            char* orow = (char*)(out_img + (size_t)(R0 + tt) * N + 8 * jj);
            *(ulonglong2*)(orow)      = make_ulonglong2(o2[0], o2[1]);
            *(ulonglong2*)(orow + 16) = make_ulonglong2(o2[2], o2[3]);
        };

        lr_part(rg,     o2a);
        lr_part(rg + 8, o2b);
    }
}

// ---------------------------------------------------------------------------
extern "C" void kernel_launch(void* const* d_in, const int* in_sizes, int n_in,
                              void* d_out, int out_size)
{
    const float* data = (const float*)d_in[0];
    float* out = (float*)d_out;
    (void)in_sizes; (void)n_in; (void)out_size;

    const int smem = (LOR + 2 * TR) * KS * (int)sizeof(float);  // 62400 B
    cudaFuncSetAttribute(k_all, cudaFuncAttributeMaxDynamicSharedMemorySize,
                         smem);

    k_all<<<dim3(N / TR, NIMG), dim3(128, 4), smem>>>(data, out);
}